// round 2
// baseline (speedup 1.0000x reference)
#include <cuda_runtime.h>
#include <cuda_bf16.h>
#include <cstdint>
#include <cstddef>

// y[32,11008] = x[32,4096] @ (Wq * scale)^T + bias
// Base-ISA path (ptxas target sm_103, no 'a'): mma.sync m16n8k16 bf16.
// Ternary W -> bf16 exact in regs (LDG.128 -> cvt -> A-frags, no smem).
// x -> hi/lo bf16 split in smem tile (exactness to ~2^-17).
// sigma K-permutation: phys frag cols {2c,2c+1,2c+8,2c+9} -> logical {4c..4c+3}
// applied identically to A and B => all fragment loads contiguous.

#define OUTN 11008
#define INK  4096
#define TM   128
#define KC   64
#define NCHUNK (INK / KC)   // 64
#define NCTA (OUTN / TM)    // 86
#define NTHREADS 256
#define XROW 160            // padded row stride (bytes) for x smem tile

__device__ __forceinline__ uint32_t pack_bf(int x, int y) {
    __nv_bfloat162 p = __floats2bfloat162_rn((float)x, (float)y);
    return *reinterpret_cast<uint32_t*>(&p);
}

__device__ __forceinline__ void mma16816(float d[4],
                                         uint32_t a0, uint32_t a1, uint32_t a2, uint32_t a3,
                                         uint32_t b0, uint32_t b1) {
    asm volatile(
        "mma.sync.aligned.m16n8k16.row.col.f32.bf16.bf16.f32 "
        "{%0,%1,%2,%3}, {%4,%5,%6,%7}, {%8,%9}, {%0,%1,%2,%3};\n"
        : "+f"(d[0]), "+f"(d[1]), "+f"(d[2]), "+f"(d[3])
        : "r"(a0), "r"(a1), "r"(a2), "r"(a3), "r"(b0), "r"(b1));
}

struct XV { float4 a, b; };

__device__ __forceinline__ void load_w(int4 w[8], const int* p0, const int* p1, int ch) {
#pragma unroll
    for (int s = 0; s < 4; ++s) {
        w[2 * s]     = *reinterpret_cast<const int4*>(p0 + ch * KC + s * 16);
        w[2 * s + 1] = *reinterpret_cast<const int4*>(p1 + ch * KC + s * 16);
    }
}

__device__ __forceinline__ XV load_x(const float* __restrict__ X, int tid, int ch) {
    XV v;
    int f0 = tid, f1 = tid + NTHREADS;
    v.a = *reinterpret_cast<const float4*>(X + (size_t)(f0 >> 4) * INK + ch * KC + (f0 & 15) * 4);
    v.b = *reinterpret_cast<const float4*>(X + (size_t)(f1 >> 4) * INK + ch * KC + (f1 & 15) * 4);
    return v;
}

__device__ __forceinline__ void cvt_store_one(float4 u, int f, unsigned char* xb) {
    int b  = f >> 4;
    int k4 = (f & 15) * 4;
    __nv_bfloat16 h0 = __float2bfloat16_rn(u.x);
    __nv_bfloat16 h1 = __float2bfloat16_rn(u.y);
    __nv_bfloat16 h2 = __float2bfloat16_rn(u.z);
    __nv_bfloat16 h3 = __float2bfloat16_rn(u.w);
    __nv_bfloat16 l0 = __float2bfloat16_rn(u.x - __bfloat162float(h0));
    __nv_bfloat16 l1 = __float2bfloat16_rn(u.y - __bfloat162float(h1));
    __nv_bfloat16 l2 = __float2bfloat16_rn(u.z - __bfloat162float(h2));
    __nv_bfloat16 l3 = __float2bfloat16_rn(u.w - __bfloat162float(h3));
    __nv_bfloat162 hp0; hp0.x = h0; hp0.y = h1;
    __nv_bfloat162 hp1; hp1.x = h2; hp1.y = h3;
    __nv_bfloat162 lp0; lp0.x = l0; lp0.y = l1;
    __nv_bfloat162 lp1; lp1.x = l2; lp1.y = l3;
    uint2 hv = make_uint2(*reinterpret_cast<uint32_t*>(&hp0), *reinterpret_cast<uint32_t*>(&hp1));
    uint2 lv = make_uint2(*reinterpret_cast<uint32_t*>(&lp0), *reinterpret_cast<uint32_t*>(&lp1));
    *reinterpret_cast<uint2*>(xb + b * XROW + k4 * 2) = hv;
    *reinterpret_cast<uint2*>(xb + (b + 32) * XROW + k4 * 2) = lv;
}

__device__ __forceinline__ void store_x(XV v, unsigned char* xb, int tid) {
    cvt_store_one(v.a, tid, xb);
    cvt_store_one(v.b, tid + NTHREADS, xb);
}

__device__ __forceinline__ void compute(const int4 w[8], const unsigned char* xb,
                                        int lane, float acc[8][4]) {
    int rr = lane >> 2;
    int cc = lane & 3;
#pragma unroll
    for (int s = 0; s < 4; ++s) {
        int4 wa = w[2 * s];       // row r,   logical k 4c..4c+3 (per kstep)
        int4 wb = w[2 * s + 1];   // row r+8
        uint32_t a0 = pack_bf(wa.x, wa.y);
        uint32_t a2 = pack_bf(wa.z, wa.w);
        uint32_t a1 = pack_bf(wb.x, wb.y);
        uint32_t a3 = pack_bf(wb.z, wb.w);
#pragma unroll
        for (int nf = 0; nf < 8; ++nf) {
            uint2 bv = *reinterpret_cast<const uint2*>(
                xb + (nf * 8 + rr) * XROW + s * 32 + cc * 8);
            mma16816(acc[nf], a0, a1, a2, a3, bv.x, bv.y);
        }
    }
}

__global__ void __launch_bounds__(NTHREADS)
lin2b_kernel(const float* __restrict__ X, const int* __restrict__ W,
             const float* __restrict__ SC, const float* __restrict__ BI,
             float* __restrict__ OUT)
{
    __shared__ __align__(16) unsigned char xsm0[64 * XROW];
    __shared__ __align__(16) unsigned char xsm1[64 * XROW];

    int tid  = threadIdx.x;
    int wid  = tid >> 5;
    int lane = tid & 31;
    int rr   = lane >> 2;
    int cc   = lane & 3;

    int rowA = blockIdx.x * TM + wid * 16 + rr;      // rows r and r+8 of warp tile
    const int* wp0 = W + (size_t)rowA * INK + 4 * cc;
    const int* wp1 = W + (size_t)(rowA + 8) * INK + 4 * cc;

    float acc[8][4];
#pragma unroll
    for (int i = 0; i < 8; ++i)
#pragma unroll
        for (int j = 0; j < 4; ++j) acc[i][j] = 0.0f;

    int4 w0[8], w1[8];

    // prologue: chunk 0 W into w0, x chunk 0 into xsm0
    load_w(w0, wp0, wp1, 0);
    {
        XV v = load_x(X, tid, 0);
        store_x(v, xsm0, tid);
    }
    __syncthreads();

#pragma unroll 1
    for (int ch = 0; ch < NCHUNK; ch += 2) {
        // even half: consume w0/xsm0, prefetch ch+1 into w1/xsm1
        {
            load_w(w1, wp0, wp1, ch + 1);
            XV v = load_x(X, tid, ch + 1);
            compute(w0, xsm0, lane, acc);
            store_x(v, xsm1, tid);
            __syncthreads();
        }
        // odd half: consume w1/xsm1, prefetch ch+2 into w0/xsm0
        {
            XV v;
            bool more = (ch + 2) < NCHUNK;
            if (more) {
                load_w(w0, wp0, wp1, ch + 2);
                v = load_x(X, tid, ch + 2);
            }
            compute(w1, xsm1, lane, acc);
            if (more) {
                store_x(v, xsm0, tid);
            }
            __syncthreads();
        }
    }

    // ---- epilogue: acc[nf] (hi) + acc[nf+4] (lo), scale + bias, store ----
    int o0 = rowA;
    int o1 = rowA + 8;
    float s0 = SC[o0], bi0 = BI[o0];
    float s1 = SC[o1], bi1 = BI[o1];
#pragma unroll
    for (int nf = 0; nf < 4; ++nf) {
        int b0 = nf * 8 + 2 * cc;
        int b1 = b0 + 1;
        float v00 = acc[nf][0] + acc[nf + 4][0];   // D[r][b0]
        float v01 = acc[nf][1] + acc[nf + 4][1];   // D[r][b1]
        float v10 = acc[nf][2] + acc[nf + 4][2];   // D[r+8][b0]
        float v11 = acc[nf][3] + acc[nf + 4][3];   // D[r+8][b1]
        OUT[(size_t)b0 * OUTN + o0] = fmaf(s0, v00, bi0);
        OUT[(size_t)b1 * OUTN + o0] = fmaf(s0, v01, bi0);
        OUT[(size_t)b0 * OUTN + o1] = fmaf(s1, v10, bi1);
        OUT[(size_t)b1 * OUTN + o1] = fmaf(s1, v11, bi1);
    }
}

extern "C" void kernel_launch(void* const* d_in, const int* in_sizes, int n_in,
                              void* d_out, int out_size) {
    (void)in_sizes; (void)n_in; (void)out_size;
    const float* x  = (const float*)d_in[0];
    const int*   wq = (const int*)d_in[1];
    const float* sc = (const float*)d_in[2];
    const float* bi = (const float*)d_in[3];
    float* out = (float*)d_out;

    lin2b_kernel<<<NCTA, NTHREADS>>>(x, wq, sc, bi, out);
}